// round 11
// baseline (speedup 1.0000x reference)
#include <cuda_runtime.h>
#include <math.h>

#define HW 1024
#define BB 16
#define NHH 64
#define GP 7340032ull      // one gate-part: 16b * 7gb * 64co * 1024pix

typedef unsigned long long ull;

// ------------------------------ device state -------------------------------
__device__ float g_h[4 * BB * NHH * HW];
__device__ float g_c[4 * BB * NHH * HW];
__device__ float g_m[BB * NHH * HW];
__device__ float g_net[BB * 16 * HW];
__device__ float g_xgen[BB * 16 * HW];
__device__ float g_mem[BB * 2 * NHH * HW];
__device__ float g_gates[4 * BB * 7 * NHH * HW];    // 4 K-split partial sums

// repacked weights, layout [..][ci][k][co] with co contiguous
__device__ float g_Wx0R[7 * 16 * 25 * 64];          // 716800
__device__ float g_WxrR[3 * 7 * 64 * 25 * 64];      // 2150400
__device__ float g_WhR[4 * 4 * 64 * 25 * 64];       // 1638400
__device__ float g_WmR[4 * 3 * 64 * 25 * 64];       // 1228800
__device__ float g_WoR[4 * 128 * 25 * 64];          // 819200
__device__ float g_WlR[4 * 128 * 64];               // 32768
__device__ float g_WlastR[64 * 16];                 // 1024

// ----------------------------- f32x2 helpers -------------------------------
__device__ __forceinline__ ull pack2(float x) {
    ull r;
    asm("mov.b64 %0, {%1,%1};" : "=l"(r) : "r"(__float_as_uint(x)));
    return r;
}
__device__ __forceinline__ void fma2(ull& d, ull a, ull b) {
    asm("fma.rn.f32x2 %0, %1, %2, %0;" : "+l"(d) : "l"(a), "l"(b));
}
__device__ __forceinline__ float2 unpack2(ull v) {
    unsigned lo, hi;
    asm("mov.b64 {%0,%1}, %2;" : "=r"(lo), "=r"(hi) : "l"(v));
    return make_float2(__uint_as_float(lo), __uint_as_float(hi));
}
__device__ __forceinline__ float sigf(float x) { return 1.f / (1.f + __expf(-x)); }

// ------------------- init: zero state + repack all weights -----------------
__global__ void init_all(const float* __restrict__ wx0, const float* __restrict__ wxr,
                         const float* __restrict__ wh,  const float* __restrict__ wm,
                         const float* __restrict__ wo,  const float* __restrict__ wl,
                         const float* __restrict__ wlast) {
    int i = blockIdx.x * 256 + threadIdx.x;      // 4,194,304 threads
    if (i < 4 * BB * NHH * HW) { g_h[i] = 0.f; g_c[i] = 0.f; }
    if (i < BB * NHH * HW) g_m[i] = 0.f;
    if (i < BB * 16 * HW) g_xgen[i] = 0.f;
    if (i < 716800) {
        int co = i & 63, t = i >> 6, k = t % 25; t /= 25;
        int ci = t & 15, gb = t >> 4;
        g_Wx0R[i] = wx0[((gb * 64 + co) * 16 + ci) * 25 + k];
    }
    if (i < 2150400) {
        int co = i & 63, t = i >> 6, k = t % 25; t /= 25;
        int ci = t & 63; t >>= 6;
        int gb = t % 7, l3 = t / 7;
        g_WxrR[i] = wxr[(((size_t)l3 * 448 + gb * 64 + co) * 64 + ci) * 25 + k];
    }
    if (i < 1638400) {
        int co = i & 63, t = i >> 6, k = t % 25; t /= 25;
        int ci = t & 63; t >>= 6;
        int blk = t & 3, l = t >> 2;
        g_WhR[i] = wh[(((size_t)l * 256 + blk * 64 + co) * 64 + ci) * 25 + k];
    }
    if (i < 1228800) {
        int co = i & 63, t = i >> 6, k = t % 25; t /= 25;
        int ci = t & 63; t >>= 6;
        int blk = t % 3, l = t / 3;
        g_WmR[i] = wm[(((size_t)l * 192 + blk * 64 + co) * 64 + ci) * 25 + k];
    }
    if (i < 819200) {
        int co = i & 63, t = i >> 6, k = t % 25; t /= 25;
        int ci = t & 127, l = t >> 7;
        g_WoR[i] = wo[(((size_t)l * 64 + co) * 128 + ci) * 25 + k];
    }
    if (i < 32768) {
        int co = i & 63, t = i >> 6, ci = t & 127, l = t >> 7;
        g_WlR[i] = wl[((size_t)l * 64 + co) * 128 + ci];
    }
    if (i < 1024) {
        g_WlastR[i] = wlast[(i & 15) * 64 + (i >> 4)];
    }
}

// --------------------------- K0: input blend -------------------------------
__global__ void k0_net(const float* __restrict__ frames,
                       const float* __restrict__ mask, int t) {
    int i = blockIdx.x * 256 + threadIdx.x;       // 262144
    int b = i >> 14, rem = i & 16383;
    float f = frames[((size_t)b * 20 + t) * 16384 + rem];
    float v = f;
    if (t >= 10) {
        float mk = mask[((size_t)b * 9 + (t - 10)) * 16384 + rem];
        v = mk * f + (1.f - mk) * g_xgen[i];
    }
    g_net[i] = v;
}

// ---------------------- K1: fused gate convolutions ------------------------
// Persistent: 444 CTAs (148 SM x occ 3) stride over 3584 items.
// item = p*896 + b*56 + xi; xi = gb*8 + cotile. Full 32x32 image per item,
// 8 couts, K-dim split in 4 (p), double-buffered smem, register row-window.
__global__ __launch_bounds__(256, 3) void k1_gates(int l) {
    __shared__ __align__(16) float s_in[2][1296];   // 36x36 halo tile
    __shared__ __align__(16) float s_w[2][200];     // 25 k x 8 couts
    const int tid = threadIdx.x;
    const int tx = tid & 31, ty = tid >> 5;

    // precomputed fill coordinates: slot q handles s_in index tid+256q
    int foff[6];
#pragma unroll
    for (int q = 0; q < 6; q++) {
        int idx = tid + 256 * q;
        int r = idx / 36, c2 = idx - r * 36;
        int gy = r - 2, gx = c2 - 2;
        foff[q] = ((unsigned)gy < 32u && (unsigned)gx < 32u) ? ((gy << 5) + gx) : -1;
    }

    for (int item = blockIdx.x; item < 3584; item += 444) {
        const int p = item / 896;
        int rem = item - p * 896;
        const int b = rem / 56;
        const int xi = rem - b * 56;
        const int gb = xi >> 3, co0 = (xi & 7) << 3;

        // select conv (x vs h/m) and ci half
        const float *X, *W; int nc;
        if ((p >> 1) == 0) {
            if (l == 0) { X = g_net + b * 16 * HW; nc = 16; W = g_Wx0R + gb * 25600; }
            else { X = g_h + (size_t)(l - 1) * 1048576 + b * 65536; nc = 64;
                   W = g_WxrR + (size_t)(l - 1) * 716800 + gb * 102400; }
        } else {
            nc = 64;
            if (gb < 3)      { X = g_h + (size_t)l * 1048576 + b * 65536;
                               W = g_WhR + l * 409600 + gb * 102400; }
            else if (gb < 6) { X = g_m + b * 65536;
                               W = g_WmR + l * 307200 + (gb - 3) * 102400; }
            else             { X = g_h + (size_t)l * 1048576 + b * 65536;
                               W = g_WhR + l * 409600 + 3 * 102400; }
        }
        const int nh = nc >> 1;
        X += (p & 1) * nh * HW;
        W += (p & 1) * nh * 1600;

        ull acc[4][4];
#pragma unroll
        for (int j = 0; j < 4; j++)
#pragma unroll
            for (int q = 0; q < 4; q++) acc[j][q] = 0ull;

        float pv[6], pw;
        // prologue: stage ci=0 into buffer 0
#pragma unroll
        for (int q = 0; q < 6; q++) pv[q] = (foff[q] >= 0) ? X[foff[q]] : 0.f;
        pw = (tid < 200) ? W[(tid >> 3) * 64 + co0 + (tid & 7)] : 0.f;
#pragma unroll
        for (int q = 0; q < 5; q++) s_in[0][tid + 256 * q] = pv[q];
        if (tid < 16) s_in[0][tid + 1280] = pv[5];
        if (tid < 200) s_w[0][tid] = pw;
        __syncthreads();

        for (int ci = 0; ci < nh; ci++) {
            const int cur = ci & 1, nxt = cur ^ 1;
            const bool more = (ci + 1 < nh);
            if (more) {                                   // prefetch ci+1
                const float* img = X + (ci + 1) * HW;
                const float* wp  = W + (ci + 1) * 1600;
#pragma unroll
                for (int q = 0; q < 6; q++) pv[q] = (foff[q] >= 0) ? img[foff[q]] : 0.f;
                pw = (tid < 200) ? wp[(tid >> 3) * 64 + co0 + (tid & 7)] : 0.f;
            }
            const float* si = s_in[cur] + 4 * ty * 36 + tx;
            const float* swp = s_w[cur];
#pragma unroll
            for (int kx = 0; kx < 5; kx++) {
                ull wv[8];                                // 8-row column window
#pragma unroll
                for (int d = 0; d < 8; d++)
                    wv[d] = pack2(si[d * 36 + kx]);
#pragma unroll
                for (int ky = 0; ky < 5; ky++) {
                    const ulonglong2* wq = (const ulonglong2*)(swp + (ky * 5 + kx) * 8);
                    ulonglong2 wA = wq[0], wB = wq[1];
#pragma unroll
                    for (int jj = 0; jj < 4; jj++) {
                        ull vv = wv[jj + ky];
                        fma2(acc[jj][0], vv, wA.x); fma2(acc[jj][1], vv, wA.y);
                        fma2(acc[jj][2], vv, wB.x); fma2(acc[jj][3], vv, wB.y);
                    }
                }
            }
            if (more) {                                   // stage ci+1
#pragma unroll
                for (int q = 0; q < 5; q++) s_in[nxt][tid + 256 * q] = pv[q];
                if (tid < 16) s_in[nxt][tid + 1280] = pv[5];
                if (tid < 200) s_w[nxt][tid] = pw;
            }
            __syncthreads();
        }

        float* out = g_gates + (size_t)p * GP + ((size_t)(b * 7 + gb) * 64 + co0) * HW;
#pragma unroll
        for (int jj = 0; jj < 4; jj++) {
            int pix = (4 * ty + jj) * 32 + tx;
#pragma unroll
            for (int q = 0; q < 4; q++) {
                float2 f = unpack2(acc[jj][q]);
                out[(2 * q) * HW + pix] = f.x;
                out[(2 * q + 1) * HW + pix] = f.y;
            }
        }
        // no extra sync needed: next prologue writes s_in[0] only after
        // the final __syncthreads() above, when all compute reads are done
    }
}

// ------------------ K2: gate nonlinearities, c/m update --------------------
__global__ void k2_state(int l) {
    int i = blockIdx.x * 256 + threadIdx.x;        // 1048576
    int b = i >> 16, off2 = i & 65535;
    const float* G0 = g_gates + (size_t)b * 458752;
    float pi = 0.f, pf = 0.f, pg = 0.f, pip = 0.f, pfp = 0.f, pgp = 0.f;
#pragma unroll
    for (int p = 0; p < 4; p++) {
        const float* G = G0 + (size_t)p * GP;
        pi  += G[off2];
        pf  += G[65536 + off2];
        pg  += G[131072 + off2];
        pip += G[196608 + off2];
        pfp += G[262144 + off2];
        pgp += G[327680 + off2];
    }
    float* cp = g_c + (size_t)l * 1048576;
    float cn = sigf(pf + 1.f) * cp[i] + sigf(pi) * tanhf(pg);
    float mn = sigf(pfp + 1.f) * g_m[i] + sigf(pip) * tanhf(pgp);
    cp[i] = cn;
    g_m[i] = mn;
    float* mem = g_mem + (size_t)b * 131072;
    mem[off2] = cn;
    mem[65536 + off2] = mn;
}

// ------------- K3: conv_o (5x5, cin=128) + conv_l (1x1) + gate --------------
// Double-buffered; half image (16 rows) x 8 couts per CTA.
__global__ __launch_bounds__(256, 2) void k3_output(int l) {
    __shared__ __align__(16) float s_in[2][720];    // 20x36 halo tile
    __shared__ __align__(16) float s_w5[2][200];
    __shared__ __align__(16) float s_w1[2][8];
    const int tid = threadIdx.x, b = blockIdx.y;
    const int ct = blockIdx.x >> 1, sp = blockIdx.x & 1;
    const int co0 = ct << 3, y0 = sp << 4;
    const int tx = tid & 31, ty = tid >> 5;

    int foff[3];
#pragma unroll
    for (int q = 0; q < 3; q++) {
        int idx = tid + 256 * q;
        int r = idx / 36, c2 = idx - r * 36;
        int gy = y0 + r - 2, gx = c2 - 2;
        foff[q] = (idx < 720 && (unsigned)gy < 32u && (unsigned)gx < 32u)
                      ? ((gy << 5) + gx) : -1;
    }

    ull acc5[2][4], acc1[2][4];
#pragma unroll
    for (int j = 0; j < 2; j++)
#pragma unroll
        for (int q = 0; q < 4; q++) { acc5[j][q] = 0ull; acc1[j][q] = 0ull; }

    const float* src = g_mem + (size_t)b * 131072;
    const float* Wo = g_WoR + l * 204800;
    const float* Wl = g_WlR + l * 8192;

    float pv[3], pw5, pw1;
#pragma unroll
    for (int q = 0; q < 3; q++) pv[q] = (foff[q] >= 0) ? src[foff[q]] : 0.f;
    pw5 = (tid < 200) ? Wo[(tid >> 3) * 64 + co0 + (tid & 7)] : 0.f;
    pw1 = (tid < 8) ? Wl[co0 + tid] : 0.f;
#pragma unroll
    for (int q = 0; q < 2; q++) s_in[0][tid + 256 * q] = pv[q];
    if (tid < 208) s_in[0][tid + 512] = pv[2];
    if (tid < 200) s_w5[0][tid] = pw5;
    if (tid < 8) s_w1[0][tid] = pw1;
    __syncthreads();

    for (int ci = 0; ci < 128; ci++) {
        const int cur = ci & 1, nxt = cur ^ 1;
        const bool more = (ci + 1 < 128);
        if (more) {
            const float* img = src + (ci + 1) * HW;
#pragma unroll
            for (int q = 0; q < 3; q++) pv[q] = (foff[q] >= 0) ? img[foff[q]] : 0.f;
            pw5 = (tid < 200) ? Wo[(ci + 1) * 1600 + (tid >> 3) * 64 + co0 + (tid & 7)] : 0.f;
            pw1 = (tid < 8) ? Wl[(ci + 1) * 64 + co0 + tid] : 0.f;
        }
        const float* si = s_in[cur];
        const float* swp = s_w5[cur];
        ulonglong2 w1a = ((const ulonglong2*)s_w1[cur])[0];
        ulonglong2 w1b = ((const ulonglong2*)s_w1[cur])[1];
#pragma unroll
        for (int ky = 0; ky < 5; ky++) {
#pragma unroll
            for (int kx = 0; kx < 5; kx++) {
                const ulonglong2* wq = (const ulonglong2*)(swp + (ky * 5 + kx) * 8);
                ulonglong2 wA = wq[0], wB = wq[1];
#pragma unroll
                for (int j = 0; j < 2; j++) {
                    ull vv = pack2(si[(ty + 8 * j + ky) * 36 + tx + kx]);
                    fma2(acc5[j][0], vv, wA.x); fma2(acc5[j][1], vv, wA.y);
                    fma2(acc5[j][2], vv, wB.x); fma2(acc5[j][3], vv, wB.y);
                }
            }
        }
#pragma unroll
        for (int j = 0; j < 2; j++) {
            ull vv = pack2(si[(ty + 8 * j + 2) * 36 + tx + 2]);
            fma2(acc1[j][0], vv, w1a.x); fma2(acc1[j][1], vv, w1a.y);
            fma2(acc1[j][2], vv, w1b.x); fma2(acc1[j][3], vv, w1b.y);
        }
        if (more) {
#pragma unroll
            for (int q = 0; q < 2; q++) s_in[nxt][tid + 256 * q] = pv[q];
            if (tid < 208) s_in[nxt][tid + 512] = pv[2];
            if (tid < 200) s_w5[nxt][tid] = pw5;
            if (tid < 8) s_w1[nxt][tid] = pw1;
        }
        __syncthreads();
    }

    const float* G6 = g_gates + (size_t)b * 458752 + 393216;   // o-gate plane
    float* hp = g_h + (size_t)l * 1048576 + (size_t)b * 65536;
#pragma unroll
    for (int j = 0; j < 2; j++) {
        int pix = (y0 + ty + 8 * j) * 32 + tx;
#pragma unroll
        for (int q = 0; q < 4; q++) {
            float2 f5 = unpack2(acc5[j][q]);
            float2 f1 = unpack2(acc1[j][q]);
            int c0 = co0 + 2 * q, c1 = c0 + 1;
            float ox0 = f5.x, ox1 = f5.y;
#pragma unroll
            for (int pp = 0; pp < 4; pp++) {
                ox0 += G6[(size_t)pp * GP + c0 * HW + pix];
                ox1 += G6[(size_t)pp * GP + c1 * HW + pix];
            }
            hp[c0 * HW + pix] = sigf(ox0) * tanhf(f1.x);
            hp[c1 * HW + pix] = sigf(ox1) * tanhf(f1.y);
        }
    }
}

// -------------------- K4: 1x1 output head + x_gen stash --------------------
__global__ void k4_xgen(float* __restrict__ dout, int t) {
    __shared__ float sw[1024];
    int tid = threadIdx.x;
#pragma unroll
    for (int q = 0; q < 4; q++) sw[tid + q * 256] = g_WlastR[tid + q * 256];
    __syncthreads();
    int gi = blockIdx.x * 256 + tid;              // 16384 threads
    int pix = gi & 1023, b = gi >> 10;
    const float* h3 = g_h + 3 * 1048576 + (size_t)b * 65536 + pix;
    float acc[16];
#pragma unroll
    for (int c = 0; c < 16; c++) acc[c] = 0.f;
    for (int ci = 0; ci < 64; ci++) {
        float hv = h3[ci * HW];
        const float* w = sw + ci * 16;
#pragma unroll
        for (int c = 0; c < 16; c++) acc[c] = fmaf(hv, w[c], acc[c]);
    }
    float* xg = g_xgen + (size_t)b * 16384 + pix;
    float* op = dout + ((size_t)(b * 19 + t) * 16) * HW + pix;
#pragma unroll
    for (int c = 0; c < 16; c++) {
        xg[c * HW] = acc[c];
        op[c * HW] = acc[c];
    }
}

// --------------------------------- launch ----------------------------------
extern "C" void kernel_launch(void* const* d_in, const int* in_sizes, int n_in,
                              void* d_out, int out_size) {
    (void)in_sizes; (void)n_in; (void)out_size;
    const float* frames = (const float*)d_in[0];
    const float* mask   = (const float*)d_in[1];

    init_all<<<16384, 256>>>((const float*)d_in[2], (const float*)d_in[3],
                             (const float*)d_in[4], (const float*)d_in[5],
                             (const float*)d_in[6], (const float*)d_in[7],
                             (const float*)d_in[8]);

    float* out = (float*)d_out;
    for (int t = 0; t < 19; t++) {
        k0_net<<<1024, 256>>>(frames, mask, t);
        for (int l = 0; l < 4; l++) {
            k1_gates<<<444, 256>>>(l);
            k2_state<<<4096, 256>>>(l);
            k3_output<<<dim3(16, 16), 256>>>(l);
        }
        k4_xgen<<<64, 256>>>(out, t);
    }
}

// round 13
// speedup vs baseline: 1.0803x; 1.0803x over previous
#include <cuda_runtime.h>
#include <math.h>

#define HW 1024
#define BB 16
#define NHH 64
#define GP 7340032ull      // one gate-part: 16b * 7gb * 64co * 1024pix
#define NPARTS 8

typedef unsigned long long ull;

// ------------------------------ device state -------------------------------
__device__ float g_h[4 * BB * NHH * HW];
__device__ float g_c[4 * BB * NHH * HW];
__device__ float g_m[BB * NHH * HW];
__device__ float g_net[BB * 16 * HW];
__device__ float g_xgen[BB * 16 * HW];
__device__ float g_mem[BB * 2 * NHH * HW];
__device__ float g_gates[NPARTS * BB * 7 * NHH * HW];   // 8 K-split partial sums

// repacked weights, layout [..][ci][k][co] with co contiguous
__device__ float g_Wx0R[7 * 16 * 25 * 64];          // 179200
__device__ float g_WxrR[3 * 7 * 64 * 25 * 64];      // 2150400
__device__ float g_WhR[4 * 4 * 64 * 25 * 64];       // 1638400
__device__ float g_WmR[4 * 3 * 64 * 25 * 64];       // 1228800
__device__ float g_WoR[4 * 128 * 25 * 64];          // 819200
__device__ float g_WlR[4 * 128 * 64];               // 32768
__device__ float g_WlastR[64 * 16];                 // 1024

// ----------------------------- f32x2 helpers -------------------------------
__device__ __forceinline__ ull pack2(float x) {
    ull r;
    asm("mov.b64 %0, {%1,%1};" : "=l"(r) : "r"(__float_as_uint(x)));
    return r;
}
__device__ __forceinline__ void fma2(ull& d, ull a, ull b) {
    asm("fma.rn.f32x2 %0, %1, %2, %0;" : "+l"(d) : "l"(a), "l"(b));
}
__device__ __forceinline__ float2 unpack2(ull v) {
    unsigned lo, hi;
    asm("mov.b64 {%0,%1}, %2;" : "=r"(lo), "=r"(hi) : "l"(v));
    return make_float2(__uint_as_float(lo), __uint_as_float(hi));
}
__device__ __forceinline__ float sigf(float x) { return 1.f / (1.f + __expf(-x)); }

// ------------------- init: zero state + repack all weights -----------------
__global__ void init_all(const float* __restrict__ wx0, const float* __restrict__ wxr,
                         const float* __restrict__ wh,  const float* __restrict__ wm,
                         const float* __restrict__ wo,  const float* __restrict__ wl,
                         const float* __restrict__ wlast) {
    int i = blockIdx.x * 256 + threadIdx.x;      // 4,194,304 threads
    if (i < 4 * BB * NHH * HW) { g_h[i] = 0.f; g_c[i] = 0.f; }
    if (i < BB * NHH * HW) g_m[i] = 0.f;
    if (i < BB * 16 * HW) g_xgen[i] = 0.f;
    if (i < 179200) {                            // 7*16*25*64 (was wrongly 716800)
        int co = i & 63, t = i >> 6, k = t % 25; t /= 25;
        int ci = t & 15, gb = t >> 4;
        g_Wx0R[i] = wx0[((gb * 64 + co) * 16 + ci) * 25 + k];
    }
    if (i < 2150400) {
        int co = i & 63, t = i >> 6, k = t % 25; t /= 25;
        int ci = t & 63; t >>= 6;
        int gb = t % 7, l3 = t / 7;
        g_WxrR[i] = wxr[(((size_t)l3 * 448 + gb * 64 + co) * 64 + ci) * 25 + k];
    }
    if (i < 1638400) {
        int co = i & 63, t = i >> 6, k = t % 25; t /= 25;
        int ci = t & 63; t >>= 6;
        int blk = t & 3, l = t >> 2;
        g_WhR[i] = wh[(((size_t)l * 256 + blk * 64 + co) * 64 + ci) * 25 + k];
    }
    if (i < 1228800) {
        int co = i & 63, t = i >> 6, k = t % 25; t /= 25;
        int ci = t & 63; t >>= 6;
        int blk = t % 3, l = t / 3;
        g_WmR[i] = wm[(((size_t)l * 192 + blk * 64 + co) * 64 + ci) * 25 + k];
    }
    if (i < 819200) {
        int co = i & 63, t = i >> 6, k = t % 25; t /= 25;
        int ci = t & 127, l = t >> 7;
        g_WoR[i] = wo[(((size_t)l * 64 + co) * 128 + ci) * 25 + k];
    }
    if (i < 32768) {
        int co = i & 63, t = i >> 6, ci = t & 127, l = t >> 7;
        g_WlR[i] = wl[((size_t)l * 64 + co) * 128 + ci];
    }
    if (i < 1024) {
        g_WlastR[i] = wlast[(i & 15) * 64 + (i >> 4)];
    }
}

// --------------------------- K0: input blend -------------------------------
__global__ void k0_net(const float* __restrict__ frames,
                       const float* __restrict__ mask, int t) {
    int i = blockIdx.x * 256 + threadIdx.x;       // 262144
    int b = i >> 14, rem = i & 16383;
    float f = frames[((size_t)b * 20 + t) * 16384 + rem];
    float v = f;
    if (t >= 10) {
        float mk = mask[((size_t)b * 9 + (t - 10)) * 16384 + rem];
        v = mk * f + (1.f - mk) * g_xgen[i];
    }
    g_net[i] = v;
}

// ---------------------- K1: fused gate convolutions ------------------------
// Full 32x32 image per CTA, 16 couts per CTA (occ 2), double-buffered smem.
// K-dim split in 8: p>>2 selects x-conv vs h/m-conv, p&3 selects ci quarter.
// grid (28, 16, 8): x -> gb(0..6) x cout-tile(0..3); y = batch; z = part.
__global__ __launch_bounds__(256, 2) void k1_gates(int l) {
    __shared__ __align__(16) float s_in[2][1296];   // 36x36 halo tile
    __shared__ __align__(16) float s_w[2][400];     // 25 k x 16 couts
    const int tid = threadIdx.x, b = blockIdx.y, p = blockIdx.z;
    const int gb = blockIdx.x >> 2, co0 = (blockIdx.x & 3) << 4;
    const int tx = tid & 31, ty = tid >> 5;

    // precomputed fill coordinates: slot q handles s_in index tid+256q
    int foff[6];
#pragma unroll
    for (int q = 0; q < 6; q++) {
        int idx = tid + 256 * q;
        int r = idx / 36, c2 = idx - r * 36;
        int gy = r - 2, gx = c2 - 2;
        foff[q] = ((unsigned)gy < 32u && (unsigned)gx < 32u) ? ((gy << 5) + gx) : -1;
    }

    // select conv (x vs h/m) and ci quarter
    const float *X, *W; int nc;
    if ((p >> 2) == 0) {
        if (l == 0) { X = g_net + b * 16 * HW; nc = 16; W = g_Wx0R + gb * 25600; }
        else { X = g_h + (size_t)(l - 1) * 1048576 + b * 65536; nc = 64;
               W = g_WxrR + (size_t)(l - 1) * 716800 + gb * 102400; }
    } else {
        nc = 64;
        if (gb < 3)      { X = g_h + (size_t)l * 1048576 + b * 65536;
                           W = g_WhR + l * 409600 + gb * 102400; }
        else if (gb < 6) { X = g_m + b * 65536;
                           W = g_WmR + l * 307200 + (gb - 3) * 102400; }
        else             { X = g_h + (size_t)l * 1048576 + b * 65536;
                           W = g_WhR + l * 409600 + 3 * 102400; }
    }
    const int nq = nc >> 2;
    X += (p & 3) * nq * HW;
    W += (p & 3) * nq * 1600;

    ull acc[4][8];
#pragma unroll
    for (int j = 0; j < 4; j++)
#pragma unroll
        for (int q = 0; q < 8; q++) acc[j][q] = 0ull;

    float pv[6], pw0, pw1;
    // prologue: stage ci=0 into buffer 0
#pragma unroll
    for (int q = 0; q < 6; q++) pv[q] = (foff[q] >= 0) ? X[foff[q]] : 0.f;
    pw0 = W[(tid >> 4) * 64 + co0 + (tid & 15)];
    { int i2 = tid + 256;
      pw1 = (i2 < 400) ? W[(i2 >> 4) * 64 + co0 + (i2 & 15)] : 0.f; }
#pragma unroll
    for (int q = 0; q < 5; q++) s_in[0][tid + 256 * q] = pv[q];
    if (tid < 16) s_in[0][tid + 1280] = pv[5];
    s_w[0][tid] = pw0;
    if (tid < 144) s_w[0][tid + 256] = pw1;
    __syncthreads();

    for (int ci = 0; ci < nq; ci++) {
        const int cur = ci & 1, nxt = cur ^ 1;
        const bool more = (ci + 1 < nq);
        if (more) {                                   // prefetch ci+1
            const float* img = X + (ci + 1) * HW;
            const float* wp  = W + (ci + 1) * 1600;
#pragma unroll
            for (int q = 0; q < 6; q++) pv[q] = (foff[q] >= 0) ? img[foff[q]] : 0.f;
            pw0 = wp[(tid >> 4) * 64 + co0 + (tid & 15)];
            { int i2 = tid + 256;
              pw1 = (i2 < 400) ? wp[(i2 >> 4) * 64 + co0 + (i2 & 15)] : 0.f; }
        }
        const float* si = s_in[cur];
        const float* swp = s_w[cur];
#pragma unroll
        for (int ky = 0; ky < 5; ky++) {
#pragma unroll
            for (int kx = 0; kx < 5; kx++) {
                const ulonglong2* wq = (const ulonglong2*)(swp + (ky * 5 + kx) * 16);
                ulonglong2 wA = wq[0], wB = wq[1], wC = wq[2], wD = wq[3];
#pragma unroll
                for (int j = 0; j < 4; j++) {
                    ull vv = pack2(si[(ty + 8 * j + ky) * 36 + tx + kx]);
                    fma2(acc[j][0], vv, wA.x); fma2(acc[j][1], vv, wA.y);
                    fma2(acc[j][2], vv, wB.x); fma2(acc[j][3], vv, wB.y);
                    fma2(acc[j][4], vv, wC.x); fma2(acc[j][5], vv, wC.y);
                    fma2(acc[j][6], vv, wD.x); fma2(acc[j][7], vv, wD.y);
                }
            }
        }
        if (more) {                                   // stage ci+1
#pragma unroll
            for (int q = 0; q < 5; q++) s_in[nxt][tid + 256 * q] = pv[q];
            if (tid < 16) s_in[nxt][tid + 1280] = pv[5];
            s_w[nxt][tid] = pw0;
            if (tid < 144) s_w[nxt][tid + 256] = pw1;
        }
        __syncthreads();
    }

    float* out = g_gates + (size_t)p * GP + ((size_t)(b * 7 + gb) * 64 + co0) * HW;
#pragma unroll
    for (int j = 0; j < 4; j++) {
        int pix = (ty + 8 * j) * 32 + tx;
#pragma unroll
        for (int q = 0; q < 8; q++) {
            float2 f = unpack2(acc[j][q]);
            out[(2 * q) * HW + pix] = f.x;
            out[(2 * q + 1) * HW + pix] = f.y;
        }
    }
}

// ------------------ K2: gate nonlinearities, c/m update --------------------
__global__ void k2_state(int l) {
    int i = blockIdx.x * 256 + threadIdx.x;        // 1048576
    int b = i >> 16, off2 = i & 65535;
    const float* G0 = g_gates + (size_t)b * 458752;
    float pi = 0.f, pf = 0.f, pg = 0.f, pip = 0.f, pfp = 0.f, pgp = 0.f;
#pragma unroll
    for (int p = 0; p < NPARTS; p++) {
        const float* G = G0 + (size_t)p * GP;
        pi  += G[off2];
        pf  += G[65536 + off2];
        pg  += G[131072 + off2];
        pip += G[196608 + off2];
        pfp += G[262144 + off2];
        pgp += G[327680 + off2];
    }
    float* cp = g_c + (size_t)l * 1048576;
    float cn = sigf(pf + 1.f) * cp[i] + sigf(pi) * tanhf(pg);
    float mn = sigf(pfp + 1.f) * g_m[i] + sigf(pip) * tanhf(pgp);
    cp[i] = cn;
    g_m[i] = mn;
    float* mem = g_mem + (size_t)b * 131072;
    mem[off2] = cn;
    mem[65536 + off2] = mn;
}

// ------------- K3: conv_o (5x5, cin=128) + conv_l (1x1) + gate --------------
// Double-buffered; half image (16 rows) x 8 couts per CTA.
__global__ __launch_bounds__(256, 2) void k3_output(int l) {
    __shared__ __align__(16) float s_in[2][720];    // 20x36 halo tile
    __shared__ __align__(16) float s_w5[2][200];
    __shared__ __align__(16) float s_w1[2][8];
    const int tid = threadIdx.x, b = blockIdx.y;
    const int ct = blockIdx.x >> 1, sp = blockIdx.x & 1;
    const int co0 = ct << 3, y0 = sp << 4;
    const int tx = tid & 31, ty = tid >> 5;

    int foff[3];
#pragma unroll
    for (int q = 0; q < 3; q++) {
        int idx = tid + 256 * q;
        int r = idx / 36, c2 = idx - r * 36;
        int gy = y0 + r - 2, gx = c2 - 2;
        foff[q] = (idx < 720 && (unsigned)gy < 32u && (unsigned)gx < 32u)
                      ? ((gy << 5) + gx) : -1;
    }

    ull acc5[2][4], acc1[2][4];
#pragma unroll
    for (int j = 0; j < 2; j++)
#pragma unroll
        for (int q = 0; q < 4; q++) { acc5[j][q] = 0ull; acc1[j][q] = 0ull; }

    const float* src = g_mem + (size_t)b * 131072;
    const float* Wo = g_WoR + l * 204800;
    const float* Wl = g_WlR + l * 8192;

    float pv[3], pw5, pw1;
#pragma unroll
    for (int q = 0; q < 3; q++) pv[q] = (foff[q] >= 0) ? src[foff[q]] : 0.f;
    pw5 = (tid < 200) ? Wo[(tid >> 3) * 64 + co0 + (tid & 7)] : 0.f;
    pw1 = (tid < 8) ? Wl[co0 + tid] : 0.f;
#pragma unroll
    for (int q = 0; q < 2; q++) s_in[0][tid + 256 * q] = pv[q];
    if (tid < 208) s_in[0][tid + 512] = pv[2];
    if (tid < 200) s_w5[0][tid] = pw5;
    if (tid < 8) s_w1[0][tid] = pw1;
    __syncthreads();

    for (int ci = 0; ci < 128; ci++) {
        const int cur = ci & 1, nxt = cur ^ 1;
        const bool more = (ci + 1 < 128);
        if (more) {
            const float* img = src + (ci + 1) * HW;
#pragma unroll
            for (int q = 0; q < 3; q++) pv[q] = (foff[q] >= 0) ? img[foff[q]] : 0.f;
            pw5 = (tid < 200) ? Wo[(ci + 1) * 1600 + (tid >> 3) * 64 + co0 + (tid & 7)] : 0.f;
            pw1 = (tid < 8) ? Wl[(ci + 1) * 64 + co0 + tid] : 0.f;
        }
        const float* si = s_in[cur];
        const float* swp = s_w5[cur];
        ulonglong2 w1a = ((const ulonglong2*)s_w1[cur])[0];
        ulonglong2 w1b = ((const ulonglong2*)s_w1[cur])[1];
#pragma unroll
        for (int ky = 0; ky < 5; ky++) {
#pragma unroll
            for (int kx = 0; kx < 5; kx++) {
                const ulonglong2* wq = (const ulonglong2*)(swp + (ky * 5 + kx) * 8);
                ulonglong2 wA = wq[0], wB = wq[1];
#pragma unroll
                for (int j = 0; j < 2; j++) {
                    ull vv = pack2(si[(ty + 8 * j + ky) * 36 + tx + kx]);
                    fma2(acc5[j][0], vv, wA.x); fma2(acc5[j][1], vv, wA.y);
                    fma2(acc5[j][2], vv, wB.x); fma2(acc5[j][3], vv, wB.y);
                }
            }
        }
#pragma unroll
        for (int j = 0; j < 2; j++) {
            ull vv = pack2(si[(ty + 8 * j + 2) * 36 + tx + 2]);
            fma2(acc1[j][0], vv, w1a.x); fma2(acc1[j][1], vv, w1a.y);
            fma2(acc1[j][2], vv, w1b.x); fma2(acc1[j][3], vv, w1b.y);
        }
        if (more) {
#pragma unroll
            for (int q = 0; q < 2; q++) s_in[nxt][tid + 256 * q] = pv[q];
            if (tid < 208) s_in[nxt][tid + 512] = pv[2];
            if (tid < 200) s_w5[nxt][tid] = pw5;
            if (tid < 8) s_w1[nxt][tid] = pw1;
        }
        __syncthreads();
    }

    const float* G6 = g_gates + (size_t)b * 458752 + 393216;   // o-gate plane
    float* hp = g_h + (size_t)l * 1048576 + (size_t)b * 65536;
#pragma unroll
    for (int j = 0; j < 2; j++) {
        int pix = (y0 + ty + 8 * j) * 32 + tx;
#pragma unroll
        for (int q = 0; q < 4; q++) {
            float2 f5 = unpack2(acc5[j][q]);
            float2 f1 = unpack2(acc1[j][q]);
            int c0 = co0 + 2 * q, c1 = c0 + 1;
            float ox0 = f5.x, ox1 = f5.y;
#pragma unroll
            for (int pp = 0; pp < NPARTS; pp++) {
                ox0 += G6[(size_t)pp * GP + c0 * HW + pix];
                ox1 += G6[(size_t)pp * GP + c1 * HW + pix];
            }
            hp[c0 * HW + pix] = sigf(ox0) * tanhf(f1.x);
            hp[c1 * HW + pix] = sigf(ox1) * tanhf(f1.y);
        }
    }
}

// -------------------- K4: 1x1 output head + x_gen stash --------------------
__global__ void k4_xgen(float* __restrict__ dout, int t) {
    __shared__ float sw[1024];
    int tid = threadIdx.x;
#pragma unroll
    for (int q = 0; q < 4; q++) sw[tid + q * 256] = g_WlastR[tid + q * 256];
    __syncthreads();
    int gi = blockIdx.x * 256 + tid;              // 16384 threads
    int pix = gi & 1023, b = gi >> 10;
    const float* h3 = g_h + 3 * 1048576 + (size_t)b * 65536 + pix;
    float acc[16];
#pragma unroll
    for (int c = 0; c < 16; c++) acc[c] = 0.f;
    for (int ci = 0; ci < 64; ci++) {
        float hv = h3[ci * HW];
        const float* w = sw + ci * 16;
#pragma unroll
        for (int c = 0; c < 16; c++) acc[c] = fmaf(hv, w[c], acc[c]);
    }
    float* xg = g_xgen + (size_t)b * 16384 + pix;
    float* op = dout + ((size_t)(b * 19 + t) * 16) * HW + pix;
#pragma unroll
    for (int c = 0; c < 16; c++) {
        xg[c * HW] = acc[c];
        op[c * HW] = acc[c];
    }
}

// --------------------------------- launch ----------------------------------
extern "C" void kernel_launch(void* const* d_in, const int* in_sizes, int n_in,
                              void* d_out, int out_size) {
    (void)in_sizes; (void)n_in; (void)out_size;
    const float* frames = (const float*)d_in[0];
    const float* mask   = (const float*)d_in[1];

    init_all<<<16384, 256>>>((const float*)d_in[2], (const float*)d_in[3],
                             (const float*)d_in[4], (const float*)d_in[5],
                             (const float*)d_in[6], (const float*)d_in[7],
                             (const float*)d_in[8]);

    float* out = (float*)d_out;
    for (int t = 0; t < 19; t++) {
        k0_net<<<1024, 256>>>(frames, mask, t);
        for (int l = 0; l < 4; l++) {
            k1_gates<<<dim3(28, 16, 8), 256>>>(l);
            k2_state<<<4096, 256>>>(l);
            k3_output<<<dim3(16, 16), 256>>>(l);
        }
        k4_xgen<<<64, 256>>>(out, t);
    }
}

// round 14
// speedup vs baseline: 1.0832x; 1.0027x over previous
#include <cuda_runtime.h>
#include <math.h>

#define HW 1024
#define BB 16
#define NHH 64
#define GP 7340032ull      // one gate-part: 16b * 7gb * 64co * 1024pix
#define NPARTS 8

typedef unsigned long long ull;

// ------------------------------ device state -------------------------------
__device__ float g_h[4 * BB * NHH * HW];
__device__ float g_c[4 * BB * NHH * HW];
__device__ float g_m[BB * NHH * HW];
__device__ float g_net[BB * 16 * HW];
__device__ float g_xgen[BB * 16 * HW];
__device__ float g_mem[BB * 2 * NHH * HW];
__device__ float g_gates[NPARTS * BB * 7 * NHH * HW];   // 8 K-split partial sums

// repacked weights, layout [..][ci][k][co] with co contiguous
__device__ float g_Wx0R[7 * 16 * 25 * 64];          // 179200
__device__ float g_WxrR[3 * 7 * 64 * 25 * 64];      // 2150400
__device__ float g_WhR[4 * 4 * 64 * 25 * 64];       // 1638400
__device__ float g_WmR[4 * 3 * 64 * 25 * 64];       // 1228800
__device__ float g_WoR[4 * 128 * 25 * 64];          // 819200
__device__ float g_WlR[4 * 128 * 64];               // 32768
__device__ float g_WlastR[64 * 16];                 // 1024

// ----------------------------- f32x2 helpers -------------------------------
__device__ __forceinline__ ull pack2(float x) {
    ull r;
    asm("mov.b64 %0, {%1,%1};" : "=l"(r) : "r"(__float_as_uint(x)));
    return r;
}
__device__ __forceinline__ void fma2(ull& d, ull a, ull b) {
    asm("fma.rn.f32x2 %0, %1, %2, %0;" : "+l"(d) : "l"(a), "l"(b));
}
__device__ __forceinline__ float2 unpack2(ull v) {
    unsigned lo, hi;
    asm("mov.b64 {%0,%1}, %2;" : "=r"(lo), "=r"(hi) : "l"(v));
    return make_float2(__uint_as_float(lo), __uint_as_float(hi));
}
__device__ __forceinline__ float sigf(float x) { return 1.f / (1.f + __expf(-x)); }

// --------- no-op: shifts ncu capture slot (-s 5) onto k1_gates(l=0) ---------
__global__ void knop() {}

// ------------------- init: zero state + repack all weights -----------------
__global__ void init_all(const float* __restrict__ wx0, const float* __restrict__ wxr,
                         const float* __restrict__ wh,  const float* __restrict__ wm,
                         const float* __restrict__ wo,  const float* __restrict__ wl,
                         const float* __restrict__ wlast) {
    int i = blockIdx.x * 256 + threadIdx.x;      // 4,194,304 threads
    if (i < 4 * BB * NHH * HW) { g_h[i] = 0.f; g_c[i] = 0.f; }
    if (i < BB * NHH * HW) g_m[i] = 0.f;
    if (i < BB * 16 * HW) g_xgen[i] = 0.f;
    if (i < 179200) {                            // 7*16*25*64
        int co = i & 63, t = i >> 6, k = t % 25; t /= 25;
        int ci = t & 15, gb = t >> 4;
        g_Wx0R[i] = wx0[((gb * 64 + co) * 16 + ci) * 25 + k];
    }
    if (i < 2150400) {
        int co = i & 63, t = i >> 6, k = t % 25; t /= 25;
        int ci = t & 63; t >>= 6;
        int gb = t % 7, l3 = t / 7;
        g_WxrR[i] = wxr[(((size_t)l3 * 448 + gb * 64 + co) * 64 + ci) * 25 + k];
    }
    if (i < 1638400) {
        int co = i & 63, t = i >> 6, k = t % 25; t /= 25;
        int ci = t & 63; t >>= 6;
        int blk = t & 3, l = t >> 2;
        g_WhR[i] = wh[(((size_t)l * 256 + blk * 64 + co) * 64 + ci) * 25 + k];
    }
    if (i < 1228800) {
        int co = i & 63, t = i >> 6, k = t % 25; t /= 25;
        int ci = t & 63; t >>= 6;
        int blk = t % 3, l = t / 3;
        g_WmR[i] = wm[(((size_t)l * 192 + blk * 64 + co) * 64 + ci) * 25 + k];
    }
    if (i < 819200) {
        int co = i & 63, t = i >> 6, k = t % 25; t /= 25;
        int ci = t & 127, l = t >> 7;
        g_WoR[i] = wo[(((size_t)l * 64 + co) * 128 + ci) * 25 + k];
    }
    if (i < 32768) {
        int co = i & 63, t = i >> 6, ci = t & 127, l = t >> 7;
        g_WlR[i] = wl[((size_t)l * 64 + co) * 128 + ci];
    }
    if (i < 1024) {
        g_WlastR[i] = wlast[(i & 15) * 64 + (i >> 4)];
    }
}

// --------------------------- K0: input blend -------------------------------
__global__ void k0_net(const float* __restrict__ frames,
                       const float* __restrict__ mask, int t) {
    int i = blockIdx.x * 256 + threadIdx.x;       // 262144
    int b = i >> 14, rem = i & 16383;
    float f = frames[((size_t)b * 20 + t) * 16384 + rem];
    float v = f;
    if (t >= 10) {
        float mk = mask[((size_t)b * 9 + (t - 10)) * 16384 + rem];
        v = mk * f + (1.f - mk) * g_xgen[i];
    }
    g_net[i] = v;
}

// ---------------------- K1: fused gate convolutions ------------------------
// Full 32x32 image per CTA, 16 couts per CTA (occ 2), double-buffered smem.
// Thread covers 4 CONSECUTIVE rows (4ty+jj) -> 8-row column window reused
// across all (ky,jj): input LDS per ci drops 100 -> 40.
// K-dim split in 8: p>>2 selects x-conv vs h/m-conv, p&3 selects ci quarter.
// grid (28, 16, 8): x -> gb(0..6) x cout-tile(0..3); y = batch; z = part.
__global__ __launch_bounds__(256, 2) void k1_gates(int l) {
    __shared__ __align__(16) float s_in[2][1296];   // 36x36 halo tile
    __shared__ __align__(16) float s_w[2][400];     // 25 k x 16 couts
    const int tid = threadIdx.x, b = blockIdx.y, p = blockIdx.z;
    const int gb = blockIdx.x >> 2, co0 = (blockIdx.x & 3) << 4;
    const int tx = tid & 31, ty = tid >> 5;

    // precomputed fill coordinates: slot q handles s_in index tid+256q
    int foff[6];
#pragma unroll
    for (int q = 0; q < 6; q++) {
        int idx = tid + 256 * q;
        int r = idx / 36, c2 = idx - r * 36;
        int gy = r - 2, gx = c2 - 2;
        foff[q] = ((unsigned)gy < 32u && (unsigned)gx < 32u) ? ((gy << 5) + gx) : -1;
    }

    // select conv (x vs h/m) and ci quarter
    const float *X, *W; int nc;
    if ((p >> 2) == 0) {
        if (l == 0) { X = g_net + b * 16 * HW; nc = 16; W = g_Wx0R + gb * 25600; }
        else { X = g_h + (size_t)(l - 1) * 1048576 + b * 65536; nc = 64;
               W = g_WxrR + (size_t)(l - 1) * 716800 + gb * 102400; }
    } else {
        nc = 64;
        if (gb < 3)      { X = g_h + (size_t)l * 1048576 + b * 65536;
                           W = g_WhR + l * 409600 + gb * 102400; }
        else if (gb < 6) { X = g_m + b * 65536;
                           W = g_WmR + l * 307200 + (gb - 3) * 102400; }
        else             { X = g_h + (size_t)l * 1048576 + b * 65536;
                           W = g_WhR + l * 409600 + 3 * 102400; }
    }
    const int nq = nc >> 2;
    X += (p & 3) * nq * HW;
    W += (p & 3) * nq * 1600;

    ull acc[4][8];
#pragma unroll
    for (int j = 0; j < 4; j++)
#pragma unroll
        for (int q = 0; q < 8; q++) acc[j][q] = 0ull;

    float pv[6], pw0, pw1;
    // prologue: stage ci=0 into buffer 0
#pragma unroll
    for (int q = 0; q < 6; q++) pv[q] = (foff[q] >= 0) ? X[foff[q]] : 0.f;
    pw0 = W[(tid >> 4) * 64 + co0 + (tid & 15)];
    { int i2 = tid + 256;
      pw1 = (i2 < 400) ? W[(i2 >> 4) * 64 + co0 + (i2 & 15)] : 0.f; }
#pragma unroll
    for (int q = 0; q < 5; q++) s_in[0][tid + 256 * q] = pv[q];
    if (tid < 16) s_in[0][tid + 1280] = pv[5];
    s_w[0][tid] = pw0;
    if (tid < 144) s_w[0][tid + 256] = pw1;
    __syncthreads();

    for (int ci = 0; ci < nq; ci++) {
        const int cur = ci & 1, nxt = cur ^ 1;
        const bool more = (ci + 1 < nq);
        if (more) {                                   // prefetch ci+1
            const float* img = X + (ci + 1) * HW;
            const float* wp  = W + (ci + 1) * 1600;
#pragma unroll
            for (int q = 0; q < 6; q++) pv[q] = (foff[q] >= 0) ? img[foff[q]] : 0.f;
            pw0 = wp[(tid >> 4) * 64 + co0 + (tid & 15)];
            { int i2 = tid + 256;
              pw1 = (i2 < 400) ? wp[(i2 >> 4) * 64 + co0 + (i2 & 15)] : 0.f; }
        }
        const float* si = s_in[cur] + (4 * ty) * 36 + tx;
        const float* swp = s_w[cur];
#pragma unroll
        for (int kx = 0; kx < 5; kx++) {
            ull wv[8];                                // 8-row column window
#pragma unroll
            for (int d = 0; d < 8; d++) wv[d] = pack2(si[d * 36 + kx]);
#pragma unroll
            for (int ky = 0; ky < 5; ky++) {
                const ulonglong2* wq = (const ulonglong2*)(swp + (ky * 5 + kx) * 16);
                ulonglong2 wA = wq[0], wB = wq[1], wC = wq[2], wD = wq[3];
#pragma unroll
                for (int jj = 0; jj < 4; jj++) {
                    ull vv = wv[jj + ky];
                    fma2(acc[jj][0], vv, wA.x); fma2(acc[jj][1], vv, wA.y);
                    fma2(acc[jj][2], vv, wB.x); fma2(acc[jj][3], vv, wB.y);
                    fma2(acc[jj][4], vv, wC.x); fma2(acc[jj][5], vv, wC.y);
                    fma2(acc[jj][6], vv, wD.x); fma2(acc[jj][7], vv, wD.y);
                }
            }
        }
        if (more) {                                   // stage ci+1
#pragma unroll
            for (int q = 0; q < 5; q++) s_in[nxt][tid + 256 * q] = pv[q];
            if (tid < 16) s_in[nxt][tid + 1280] = pv[5];
            s_w[nxt][tid] = pw0;
            if (tid < 144) s_w[nxt][tid + 256] = pw1;
        }
        __syncthreads();
    }

    float* out = g_gates + (size_t)p * GP + ((size_t)(b * 7 + gb) * 64 + co0) * HW;
#pragma unroll
    for (int jj = 0; jj < 4; jj++) {
        int pix = (4 * ty + jj) * 32 + tx;
#pragma unroll
        for (int q = 0; q < 8; q++) {
            float2 f = unpack2(acc[jj][q]);
            out[(2 * q) * HW + pix] = f.x;
            out[(2 * q + 1) * HW + pix] = f.y;
        }
    }
}

// ------------------ K2: gate nonlinearities, c/m update --------------------
__global__ void k2_state(int l) {
    int i = blockIdx.x * 256 + threadIdx.x;        // 1048576
    int b = i >> 16, off2 = i & 65535;
    const float* G0 = g_gates + (size_t)b * 458752;
    float pi = 0.f, pf = 0.f, pg = 0.f, pip = 0.f, pfp = 0.f, pgp = 0.f;
#pragma unroll
    for (int p = 0; p < NPARTS; p++) {
        const float* G = G0 + (size_t)p * GP;
        pi  += G[off2];
        pf  += G[65536 + off2];
        pg  += G[131072 + off2];
        pip += G[196608 + off2];
        pfp += G[262144 + off2];
        pgp += G[327680 + off2];
    }
    float* cp = g_c + (size_t)l * 1048576;
    float cn = sigf(pf + 1.f) * cp[i] + sigf(pi) * tanhf(pg);
    float mn = sigf(pfp + 1.f) * g_m[i] + sigf(pip) * tanhf(pgp);
    cp[i] = cn;
    g_m[i] = mn;
    float* mem = g_mem + (size_t)b * 131072;
    mem[off2] = cn;
    mem[65536 + off2] = mn;
}

// ------------- K3: conv_o (5x5, cin=128) + conv_l (1x1) + gate --------------
// Double-buffered; half image (16 rows) x 8 couts per CTA.
__global__ __launch_bounds__(256, 2) void k3_output(int l) {
    __shared__ __align__(16) float s_in[2][720];    // 20x36 halo tile
    __shared__ __align__(16) float s_w5[2][200];
    __shared__ __align__(16) float s_w1[2][8];
    const int tid = threadIdx.x, b = blockIdx.y;
    const int ct = blockIdx.x >> 1, sp = blockIdx.x & 1;
    const int co0 = ct << 3, y0 = sp << 4;
    const int tx = tid & 31, ty = tid >> 5;

    int foff[3];
#pragma unroll
    for (int q = 0; q < 3; q++) {
        int idx = tid + 256 * q;
        int r = idx / 36, c2 = idx - r * 36;
        int gy = y0 + r - 2, gx = c2 - 2;
        foff[q] = (idx < 720 && (unsigned)gy < 32u && (unsigned)gx < 32u)
                      ? ((gy << 5) + gx) : -1;
    }

    ull acc5[2][4], acc1[2][4];
#pragma unroll
    for (int j = 0; j < 2; j++)
#pragma unroll
        for (int q = 0; q < 4; q++) { acc5[j][q] = 0ull; acc1[j][q] = 0ull; }

    const float* src = g_mem + (size_t)b * 131072;
    const float* Wo = g_WoR + l * 204800;
    const float* Wl = g_WlR + l * 8192;

    float pv[3], pw5, pw1;
#pragma unroll
    for (int q = 0; q < 3; q++) pv[q] = (foff[q] >= 0) ? src[foff[q]] : 0.f;
    pw5 = (tid < 200) ? Wo[(tid >> 3) * 64 + co0 + (tid & 7)] : 0.f;
    pw1 = (tid < 8) ? Wl[co0 + tid] : 0.f;
#pragma unroll
    for (int q = 0; q < 2; q++) s_in[0][tid + 256 * q] = pv[q];
    if (tid < 208) s_in[0][tid + 512] = pv[2];
    if (tid < 200) s_w5[0][tid] = pw5;
    if (tid < 8) s_w1[0][tid] = pw1;
    __syncthreads();

    for (int ci = 0; ci < 128; ci++) {
        const int cur = ci & 1, nxt = cur ^ 1;
        const bool more = (ci + 1 < 128);
        if (more) {
            const float* img = src + (ci + 1) * HW;
#pragma unroll
            for (int q = 0; q < 3; q++) pv[q] = (foff[q] >= 0) ? img[foff[q]] : 0.f;
            pw5 = (tid < 200) ? Wo[(ci + 1) * 1600 + (tid >> 3) * 64 + co0 + (tid & 7)] : 0.f;
            pw1 = (tid < 8) ? Wl[(ci + 1) * 64 + co0 + tid] : 0.f;
        }
        const float* si = s_in[cur];
        const float* swp = s_w5[cur];
        ulonglong2 w1a = ((const ulonglong2*)s_w1[cur])[0];
        ulonglong2 w1b = ((const ulonglong2*)s_w1[cur])[1];
#pragma unroll
        for (int ky = 0; ky < 5; ky++) {
#pragma unroll
            for (int kx = 0; kx < 5; kx++) {
                const ulonglong2* wq = (const ulonglong2*)(swp + (ky * 5 + kx) * 8);
                ulonglong2 wA = wq[0], wB = wq[1];
#pragma unroll
                for (int j = 0; j < 2; j++) {
                    ull vv = pack2(si[(ty + 8 * j + ky) * 36 + tx + kx]);
                    fma2(acc5[j][0], vv, wA.x); fma2(acc5[j][1], vv, wA.y);
                    fma2(acc5[j][2], vv, wB.x); fma2(acc5[j][3], vv, wB.y);
                }
            }
        }
#pragma unroll
        for (int j = 0; j < 2; j++) {
            ull vv = pack2(si[(ty + 8 * j + 2) * 36 + tx + 2]);
            fma2(acc1[j][0], vv, w1a.x); fma2(acc1[j][1], vv, w1a.y);
            fma2(acc1[j][2], vv, w1b.x); fma2(acc1[j][3], vv, w1b.y);
        }
        if (more) {
#pragma unroll
            for (int q = 0; q < 2; q++) s_in[nxt][tid + 256 * q] = pv[q];
            if (tid < 208) s_in[nxt][tid + 512] = pv[2];
            if (tid < 200) s_w5[nxt][tid] = pw5;
            if (tid < 8) s_w1[nxt][tid] = pw1;
        }
        __syncthreads();
    }

    const float* G6 = g_gates + (size_t)b * 458752 + 393216;   // o-gate plane
    float* hp = g_h + (size_t)l * 1048576 + (size_t)b * 65536;
#pragma unroll
    for (int j = 0; j < 2; j++) {
        int pix = (y0 + ty + 8 * j) * 32 + tx;
#pragma unroll
        for (int q = 0; q < 4; q++) {
            float2 f5 = unpack2(acc5[j][q]);
            float2 f1 = unpack2(acc1[j][q]);
            int c0 = co0 + 2 * q, c1 = c0 + 1;
            float ox0 = f5.x, ox1 = f5.y;
#pragma unroll
            for (int pp = 0; pp < NPARTS; pp++) {
                ox0 += G6[(size_t)pp * GP + c0 * HW + pix];
                ox1 += G6[(size_t)pp * GP + c1 * HW + pix];
            }
            hp[c0 * HW + pix] = sigf(ox0) * tanhf(f1.x);
            hp[c1 * HW + pix] = sigf(ox1) * tanhf(f1.y);
        }
    }
}

// -------------------- K4: 1x1 output head + x_gen stash --------------------
__global__ void k4_xgen(float* __restrict__ dout, int t) {
    __shared__ float sw[1024];
    int tid = threadIdx.x;
#pragma unroll
    for (int q = 0; q < 4; q++) sw[tid + q * 256] = g_WlastR[tid + q * 256];
    __syncthreads();
    int gi = blockIdx.x * 256 + tid;              // 16384 threads
    int pix = gi & 1023, b = gi >> 10;
    const float* h3 = g_h + 3 * 1048576 + (size_t)b * 65536 + pix;
    float acc[16];
#pragma unroll
    for (int c = 0; c < 16; c++) acc[c] = 0.f;
    for (int ci = 0; ci < 64; ci++) {
        float hv = h3[ci * HW];
        const float* w = sw + ci * 16;
#pragma unroll
        for (int c = 0; c < 16; c++) acc[c] = fmaf(hv, w[c], acc[c]);
    }
    float* xg = g_xgen + (size_t)b * 16384 + pix;
    float* op = dout + ((size_t)(b * 19 + t) * 16) * HW + pix;
#pragma unroll
    for (int c = 0; c < 16; c++) {
        xg[c * HW] = acc[c];
        op[c * HW] = acc[c];
    }
}

// --------------------------------- launch ----------------------------------
extern "C" void kernel_launch(void* const* d_in, const int* in_sizes, int n_in,
                              void* d_out, int out_size) {
    (void)in_sizes; (void)n_in; (void)out_size;
    const float* frames = (const float*)d_in[0];
    const float* mask   = (const float*)d_in[1];

    init_all<<<16384, 256>>>((const float*)d_in[2], (const float*)d_in[3],
                             (const float*)d_in[4], (const float*)d_in[5],
                             (const float*)d_in[6], (const float*)d_in[7],
                             (const float*)d_in[8]);
    knop<<<1, 32>>>();   // aligns ncu capture slot (-s 5) onto k1_gates(l=0)

    float* out = (float*)d_out;
    for (int t = 0; t < 19; t++) {
        k0_net<<<1024, 256>>>(frames, mask, t);
        for (int l = 0; l < 4; l++) {
            k1_gates<<<dim3(28, 16, 8), 256>>>(l);
            k2_state<<<4096, 256>>>(l);
            k3_output<<<dim3(16, 16), 256>>>(l);
        }
        k4_xgen<<<64, 256>>>(out, t);
    }
}

// round 15
// speedup vs baseline: 1.0992x; 1.0148x over previous
#include <cuda_runtime.h>
#include <math.h>

#define HW 1024
#define BB 16
#define NHH 64
#define GP 7340032ull      // one gate-part: 16b * 7gb * 64co * 1024pix
#define NPARTS 8

typedef unsigned long long ull;

// ------------------------------ device state -------------------------------
__device__ float g_h[4 * BB * NHH * HW];
__device__ float g_c[4 * BB * NHH * HW];
__device__ float g_m[BB * NHH * HW];
__device__ float g_net[BB * 16 * HW];
__device__ float g_xgen[BB * 16 * HW];
__device__ float g_mem[BB * 2 * NHH * HW];
__device__ float g_gates[NPARTS * BB * 7 * NHH * HW];   // 8 K-split partial sums
__device__ float g_oconv[NPARTS * BB * NHH * HW];       // conv_o partials

// repacked weights, layout [..][ci][k][co] with co contiguous
__device__ float g_Wx0R[7 * 16 * 25 * 64];          // 179200
__device__ float g_WxrR[3 * 7 * 64 * 25 * 64];      // 2150400
__device__ float g_WhR[4 * 4 * 64 * 25 * 64];       // 1638400
__device__ float g_WmR[4 * 3 * 64 * 25 * 64];       // 1228800
__device__ float g_WoR[4 * 128 * 25 * 64];          // 819200
__device__ float g_WlR[4 * 128 * 64];               // 32768
__device__ float g_WlastR[64 * 16];                 // 1024

// ----------------------------- f32x2 helpers -------------------------------
__device__ __forceinline__ ull pack2(float x) {
    ull r;
    asm("mov.b64 %0, {%1,%1};" : "=l"(r) : "r"(__float_as_uint(x)));
    return r;
}
__device__ __forceinline__ void fma2(ull& d, ull a, ull b) {
    asm("fma.rn.f32x2 %0, %1, %2, %0;" : "+l"(d) : "l"(a), "l"(b));
}
__device__ __forceinline__ float2 unpack2(ull v) {
    unsigned lo, hi;
    asm("mov.b64 {%0,%1}, %2;" : "=r"(lo), "=r"(hi) : "l"(v));
    return make_float2(__uint_as_float(lo), __uint_as_float(hi));
}
__device__ __forceinline__ float sigf(float x) { return 1.f / (1.f + __expf(-x)); }

// ------------------- init: zero state + repack all weights -----------------
__global__ void init_all(const float* __restrict__ wx0, const float* __restrict__ wxr,
                         const float* __restrict__ wh,  const float* __restrict__ wm,
                         const float* __restrict__ wo,  const float* __restrict__ wl,
                         const float* __restrict__ wlast) {
    int i = blockIdx.x * 256 + threadIdx.x;      // 4,194,304 threads
    if (i < 4 * BB * NHH * HW) { g_h[i] = 0.f; g_c[i] = 0.f; }
    if (i < BB * NHH * HW) g_m[i] = 0.f;
    if (i < BB * 16 * HW) g_xgen[i] = 0.f;
    if (i < 179200) {                            // 7*16*25*64
        int co = i & 63, t = i >> 6, k = t % 25; t /= 25;
        int ci = t & 15, gb = t >> 4;
        g_Wx0R[i] = wx0[((gb * 64 + co) * 16 + ci) * 25 + k];
    }
    if (i < 2150400) {
        int co = i & 63, t = i >> 6, k = t % 25; t /= 25;
        int ci = t & 63; t >>= 6;
        int gb = t % 7, l3 = t / 7;
        g_WxrR[i] = wxr[(((size_t)l3 * 448 + gb * 64 + co) * 64 + ci) * 25 + k];
    }
    if (i < 1638400) {
        int co = i & 63, t = i >> 6, k = t % 25; t /= 25;
        int ci = t & 63; t >>= 6;
        int blk = t & 3, l = t >> 2;
        g_WhR[i] = wh[(((size_t)l * 256 + blk * 64 + co) * 64 + ci) * 25 + k];
    }
    if (i < 1228800) {
        int co = i & 63, t = i >> 6, k = t % 25; t /= 25;
        int ci = t & 63; t >>= 6;
        int blk = t % 3, l = t / 3;
        g_WmR[i] = wm[(((size_t)l * 192 + blk * 64 + co) * 64 + ci) * 25 + k];
    }
    if (i < 819200) {
        int co = i & 63, t = i >> 6, k = t % 25; t /= 25;
        int ci = t & 127, l = t >> 7;
        g_WoR[i] = wo[(((size_t)l * 64 + co) * 128 + ci) * 25 + k];
    }
    if (i < 32768) {
        int co = i & 63, t = i >> 6, ci = t & 127, l = t >> 7;
        g_WlR[i] = wl[((size_t)l * 64 + co) * 128 + ci];
    }
    if (i < 1024) {
        g_WlastR[i] = wlast[(i & 15) * 64 + (i >> 4)];
    }
}

// --------------------------- K0: input blend -------------------------------
__global__ void k0_net(const float* __restrict__ frames,
                       const float* __restrict__ mask, int t) {
    int i = blockIdx.x * 256 + threadIdx.x;       // 262144
    int b = i >> 14, rem = i & 16383;
    float f = frames[((size_t)b * 20 + t) * 16384 + rem];
    float v = f;
    if (t >= 10) {
        float mk = mask[((size_t)b * 9 + (t - 10)) * 16384 + rem];
        v = mk * f + (1.f - mk) * g_xgen[i];
    }
    g_net[i] = v;
}

// ---------------------- K1: fused gate convolutions ------------------------
// Full 32x32 image per CTA, 16 couts per CTA (occ 2), double-buffered smem.
// Thread covers 4 CONSECUTIVE rows; 8-row register column window.
// K-dim split in 8: p>>2 selects x-conv vs h/m-conv, p&3 selects ci quarter.
__global__ __launch_bounds__(256, 2) void k1_gates(int l) {
    __shared__ __align__(16) float s_in[2][1296];   // 36x36 halo tile
    __shared__ __align__(16) float s_w[2][400];     // 25 k x 16 couts
    const int tid = threadIdx.x, b = blockIdx.y, p = blockIdx.z;
    const int gb = blockIdx.x >> 2, co0 = (blockIdx.x & 3) << 4;
    const int tx = tid & 31, ty = tid >> 5;

    int foff[6];
#pragma unroll
    for (int q = 0; q < 6; q++) {
        int idx = tid + 256 * q;
        int r = idx / 36, c2 = idx - r * 36;
        int gy = r - 2, gx = c2 - 2;
        foff[q] = ((unsigned)gy < 32u && (unsigned)gx < 32u) ? ((gy << 5) + gx) : -1;
    }

    const float *X, *W; int nc;
    if ((p >> 2) == 0) {
        if (l == 0) { X = g_net + b * 16 * HW; nc = 16; W = g_Wx0R + gb * 25600; }
        else { X = g_h + (size_t)(l - 1) * 1048576 + b * 65536; nc = 64;
               W = g_WxrR + (size_t)(l - 1) * 716800 + gb * 102400; }
    } else {
        nc = 64;
        if (gb < 3)      { X = g_h + (size_t)l * 1048576 + b * 65536;
                           W = g_WhR + l * 409600 + gb * 102400; }
        else if (gb < 6) { X = g_m + b * 65536;
                           W = g_WmR + l * 307200 + (gb - 3) * 102400; }
        else             { X = g_h + (size_t)l * 1048576 + b * 65536;
                           W = g_WhR + l * 409600 + 3 * 102400; }
    }
    const int nq = nc >> 2;
    X += (p & 3) * nq * HW;
    W += (p & 3) * nq * 1600;

    ull acc[4][8];
#pragma unroll
    for (int j = 0; j < 4; j++)
#pragma unroll
        for (int q = 0; q < 8; q++) acc[j][q] = 0ull;

    float pv[6], pw0, pw1;
#pragma unroll
    for (int q = 0; q < 6; q++) pv[q] = (foff[q] >= 0) ? X[foff[q]] : 0.f;
    pw0 = W[(tid >> 4) * 64 + co0 + (tid & 15)];
    { int i2 = tid + 256;
      pw1 = (i2 < 400) ? W[(i2 >> 4) * 64 + co0 + (i2 & 15)] : 0.f; }
#pragma unroll
    for (int q = 0; q < 5; q++) s_in[0][tid + 256 * q] = pv[q];
    if (tid < 16) s_in[0][tid + 1280] = pv[5];
    s_w[0][tid] = pw0;
    if (tid < 144) s_w[0][tid + 256] = pw1;
    __syncthreads();

    for (int ci = 0; ci < nq; ci++) {
        const int cur = ci & 1, nxt = cur ^ 1;
        const bool more = (ci + 1 < nq);
        if (more) {
            const float* img = X + (ci + 1) * HW;
            const float* wp  = W + (ci + 1) * 1600;
#pragma unroll
            for (int q = 0; q < 6; q++) pv[q] = (foff[q] >= 0) ? img[foff[q]] : 0.f;
            pw0 = wp[(tid >> 4) * 64 + co0 + (tid & 15)];
            { int i2 = tid + 256;
              pw1 = (i2 < 400) ? wp[(i2 >> 4) * 64 + co0 + (i2 & 15)] : 0.f; }
        }
        const float* si = s_in[cur] + (4 * ty) * 36 + tx;
        const float* swp = s_w[cur];
#pragma unroll
        for (int kx = 0; kx < 5; kx++) {
            ull wv[8];
#pragma unroll
            for (int d = 0; d < 8; d++) wv[d] = pack2(si[d * 36 + kx]);
#pragma unroll
            for (int ky = 0; ky < 5; ky++) {
                const ulonglong2* wq = (const ulonglong2*)(swp + (ky * 5 + kx) * 16);
                ulonglong2 wA = wq[0], wB = wq[1], wC = wq[2], wD = wq[3];
#pragma unroll
                for (int jj = 0; jj < 4; jj++) {
                    ull vv = wv[jj + ky];
                    fma2(acc[jj][0], vv, wA.x); fma2(acc[jj][1], vv, wA.y);
                    fma2(acc[jj][2], vv, wB.x); fma2(acc[jj][3], vv, wB.y);
                    fma2(acc[jj][4], vv, wC.x); fma2(acc[jj][5], vv, wC.y);
                    fma2(acc[jj][6], vv, wD.x); fma2(acc[jj][7], vv, wD.y);
                }
            }
        }
        if (more) {
#pragma unroll
            for (int q = 0; q < 5; q++) s_in[nxt][tid + 256 * q] = pv[q];
            if (tid < 16) s_in[nxt][tid + 1280] = pv[5];
            s_w[nxt][tid] = pw0;
            if (tid < 144) s_w[nxt][tid + 256] = pw1;
        }
        __syncthreads();
    }

    float* out = g_gates + (size_t)p * GP + ((size_t)(b * 7 + gb) * 64 + co0) * HW;
#pragma unroll
    for (int jj = 0; jj < 4; jj++) {
        int pix = (4 * ty + jj) * 32 + tx;
#pragma unroll
        for (int q = 0; q < 8; q++) {
            float2 f = unpack2(acc[jj][q]);
            out[(2 * q) * HW + pix] = f.x;
            out[(2 * q + 1) * HW + pix] = f.y;
        }
    }
}

// ------------------ K2: gate nonlinearities, c/m update --------------------
__global__ void k2_state(int l) {
    int i = blockIdx.x * 256 + threadIdx.x;        // 1048576
    int b = i >> 16, off2 = i & 65535;
    const float* G0 = g_gates + (size_t)b * 458752;
    float pi = 0.f, pf = 0.f, pg = 0.f, pip = 0.f, pfp = 0.f, pgp = 0.f;
#pragma unroll
    for (int p = 0; p < NPARTS; p++) {
        const float* G = G0 + (size_t)p * GP;
        pi  += G[off2];
        pf  += G[65536 + off2];
        pg  += G[131072 + off2];
        pip += G[196608 + off2];
        pfp += G[262144 + off2];
        pgp += G[327680 + off2];
    }
    float* cp = g_c + (size_t)l * 1048576;
    float cn = sigf(pf + 1.f) * cp[i] + sigf(pi) * tanhf(pg);
    float mn = sigf(pfp + 1.f) * g_m[i] + sigf(pip) * tanhf(pgp);
    cp[i] = cn;
    g_m[i] = mn;
    float* mem = g_mem + (size_t)b * 131072;
    mem[off2] = cn;
    mem[65536 + off2] = mn;
}

// ------------- K3a: conv_o partials (k1-style, K-split 8x16ci) --------------
// grid (4, 16, 8): x = cotile (16 couts), y = batch, z = ci chunk of 16.
__global__ __launch_bounds__(256, 2) void k3a_oconv(int l) {
    __shared__ __align__(16) float s_in[2][1296];
    __shared__ __align__(16) float s_w[2][400];
    const int tid = threadIdx.x, b = blockIdx.y, p = blockIdx.z;
    const int co0 = blockIdx.x << 4;
    const int tx = tid & 31, ty = tid >> 5;

    int foff[6];
#pragma unroll
    for (int q = 0; q < 6; q++) {
        int idx = tid + 256 * q;
        int r = idx / 36, c2 = idx - r * 36;
        int gy = r - 2, gx = c2 - 2;
        foff[q] = ((unsigned)gy < 32u && (unsigned)gx < 32u) ? ((gy << 5) + gx) : -1;
    }

    const float* X = g_mem + (size_t)b * 131072 + p * 16 * HW;
    const float* W = g_WoR + l * 204800 + p * 16 * 1600;

    ull acc[4][8];
#pragma unroll
    for (int j = 0; j < 4; j++)
#pragma unroll
        for (int q = 0; q < 8; q++) acc[j][q] = 0ull;

    float pv[6], pw0, pw1;
#pragma unroll
    for (int q = 0; q < 6; q++) pv[q] = (foff[q] >= 0) ? X[foff[q]] : 0.f;
    pw0 = W[(tid >> 4) * 64 + co0 + (tid & 15)];
    { int i2 = tid + 256;
      pw1 = (i2 < 400) ? W[(i2 >> 4) * 64 + co0 + (i2 & 15)] : 0.f; }
#pragma unroll
    for (int q = 0; q < 5; q++) s_in[0][tid + 256 * q] = pv[q];
    if (tid < 16) s_in[0][tid + 1280] = pv[5];
    s_w[0][tid] = pw0;
    if (tid < 144) s_w[0][tid + 256] = pw1;
    __syncthreads();

    for (int ci = 0; ci < 16; ci++) {
        const int cur = ci & 1, nxt = cur ^ 1;
        const bool more = (ci + 1 < 16);
        if (more) {
            const float* img = X + (ci + 1) * HW;
            const float* wp  = W + (ci + 1) * 1600;
#pragma unroll
            for (int q = 0; q < 6; q++) pv[q] = (foff[q] >= 0) ? img[foff[q]] : 0.f;
            pw0 = wp[(tid >> 4) * 64 + co0 + (tid & 15)];
            { int i2 = tid + 256;
              pw1 = (i2 < 400) ? wp[(i2 >> 4) * 64 + co0 + (i2 & 15)] : 0.f; }
        }
        const float* si = s_in[cur] + (4 * ty) * 36 + tx;
        const float* swp = s_w[cur];
#pragma unroll
        for (int kx = 0; kx < 5; kx++) {
            ull wv[8];
#pragma unroll
            for (int d = 0; d < 8; d++) wv[d] = pack2(si[d * 36 + kx]);
#pragma unroll
            for (int ky = 0; ky < 5; ky++) {
                const ulonglong2* wq = (const ulonglong2*)(swp + (ky * 5 + kx) * 16);
                ulonglong2 wA = wq[0], wB = wq[1], wC = wq[2], wD = wq[3];
#pragma unroll
                for (int jj = 0; jj < 4; jj++) {
                    ull vv = wv[jj + ky];
                    fma2(acc[jj][0], vv, wA.x); fma2(acc[jj][1], vv, wA.y);
                    fma2(acc[jj][2], vv, wB.x); fma2(acc[jj][3], vv, wB.y);
                    fma2(acc[jj][4], vv, wC.x); fma2(acc[jj][5], vv, wC.y);
                    fma2(acc[jj][6], vv, wD.x); fma2(acc[jj][7], vv, wD.y);
                }
            }
        }
        if (more) {
#pragma unroll
            for (int q = 0; q < 5; q++) s_in[nxt][tid + 256 * q] = pv[q];
            if (tid < 16) s_in[nxt][tid + 1280] = pv[5];
            s_w[nxt][tid] = pw0;
            if (tid < 144) s_w[nxt][tid + 256] = pw1;
        }
        __syncthreads();
    }

    float* out = g_oconv + (size_t)p * 1048576 + ((size_t)b * 64 + co0) * HW;
#pragma unroll
    for (int jj = 0; jj < 4; jj++) {
        int pix = (4 * ty + jj) * 32 + tx;
#pragma unroll
        for (int q = 0; q < 8; q++) {
            float2 f = unpack2(acc[jj][q]);
            out[(2 * q) * HW + pix] = f.x;
            out[(2 * q + 1) * HW + pix] = f.y;
        }
    }
}

// ---- K3b: conv_l (1x1) + o-gate combine (k1 parts + conv_o parts) + h -----
__global__ __launch_bounds__(256) void k3b_h(int l) {
    __shared__ float sw[8192];                     // Wl[l]: [128ci][64co]
    const int tid = threadIdx.x;
    const float* Wl = g_WlR + l * 8192;
#pragma unroll
    for (int q = 0; q < 32; q++) sw[tid + q * 256] = Wl[tid + q * 256];
    __syncthreads();

    int gi = blockIdx.x * 256 + tid;               // 16384 threads
    int pix = gi & 1023, b = gi >> 10;
    const float* mem = g_mem + (size_t)b * 131072 + pix;

    ull acc[32];
#pragma unroll
    for (int q = 0; q < 32; q++) acc[q] = 0ull;
    for (int ci = 0; ci < 128; ci++) {
        ull vv = pack2(mem[ci * HW]);
        const ulonglong2* wp = (const ulonglong2*)(sw + ci * 64);
#pragma unroll
        for (int q = 0; q < 16; q++) {
            ulonglong2 w = wp[q];
            fma2(acc[2 * q], vv, w.x);
            fma2(acc[2 * q + 1], vv, w.y);
        }
    }

    const float* G6 = g_gates + (size_t)b * 458752 + 393216 + pix;  // o-gate
    const float* OC = g_oconv + (size_t)b * 65536 + pix;
    float* hp = g_h + (size_t)l * 1048576 + (size_t)b * 65536 + pix;
    for (int q = 0; q < 32; q++) {
        float2 fl = unpack2(acc[q]);
        int c0 = 2 * q, c1 = c0 + 1;
        float o0 = 0.f, o1 = 0.f;
#pragma unroll
        for (int p = 0; p < NPARTS; p++) {
            o0 += G6[(size_t)p * GP + c0 * HW] + OC[(size_t)p * 1048576 + c0 * HW];
            o1 += G6[(size_t)p * GP + c1 * HW] + OC[(size_t)p * 1048576 + c1 * HW];
        }
        hp[c0 * HW] = sigf(o0) * tanhf(fl.x);
        hp[c1 * HW] = sigf(o1) * tanhf(fl.y);
    }
}

// -------------------- K4: 1x1 output head + x_gen stash --------------------
__global__ void k4_xgen(float* __restrict__ dout, int t) {
    __shared__ float sw[1024];
    int tid = threadIdx.x;
#pragma unroll
    for (int q = 0; q < 4; q++) sw[tid + q * 256] = g_WlastR[tid + q * 256];
    __syncthreads();
    int gi = blockIdx.x * 256 + tid;              // 16384 threads
    int pix = gi & 1023, b = gi >> 10;
    const float* h3 = g_h + 3 * 1048576 + (size_t)b * 65536 + pix;
    float acc[16];
#pragma unroll
    for (int c = 0; c < 16; c++) acc[c] = 0.f;
    for (int ci = 0; ci < 64; ci++) {
        float hv = h3[ci * HW];
        const float* w = sw + ci * 16;
#pragma unroll
        for (int c = 0; c < 16; c++) acc[c] = fmaf(hv, w[c], acc[c]);
    }
    float* xg = g_xgen + (size_t)b * 16384 + pix;
    float* op = dout + ((size_t)(b * 19 + t) * 16) * HW + pix;
#pragma unroll
    for (int c = 0; c < 16; c++) {
        xg[c * HW] = acc[c];
        op[c * HW] = acc[c];
    }
}

// --------------------------------- launch ----------------------------------
extern "C" void kernel_launch(void* const* d_in, const int* in_sizes, int n_in,
                              void* d_out, int out_size) {
    (void)in_sizes; (void)n_in; (void)out_size;
    const float* frames = (const float*)d_in[0];
    const float* mask   = (const float*)d_in[1];

    init_all<<<16384, 256>>>((const float*)d_in[2], (const float*)d_in[3],
                             (const float*)d_in[4], (const float*)d_in[5],
                             (const float*)d_in[6], (const float*)d_in[7],
                             (const float*)d_in[8]);

    float* out = (float*)d_out;
    for (int t = 0; t < 19; t++) {
        k0_net<<<1024, 256>>>(frames, mask, t);
        for (int l = 0; l < 4; l++) {
            k1_gates<<<dim3(28, 16, 8), 256>>>(l);
            k2_state<<<4096, 256>>>(l);
            k3a_oconv<<<dim3(4, 16, 8), 256>>>(l);
            k3b_h<<<64, 256>>>(l);
        }
        k4_xgen<<<64, 256>>>(out, t);
    }
}